// round 5
// baseline (speedup 1.0000x reference)
#include <cuda_runtime.h>

// ---------------------------------------------------------------------------
// CharLSTMEmbedding: B=32, T=128, L=16, VOCAB=256, E=256, H=512
//
// Restructuring:
//   1. tbl[v, 0:2048] = emb[v] @ W_ih^T + (b_ih + b_hh)   (VOCAB=256 rows only)
//   2. step 0: h==0 -> pure elementwise from tbl gather
//   3. steps 1..15: gates = H @ W_hh^T (+ tbl row gather), fused LSTM epilogue
// State ping-pongs between __device__ globals; last step writes d_out.
// ---------------------------------------------------------------------------

#define BT_TOTAL 4096
#define SEQ_L    16
#define HDIM     512
#define EDIM     256
#define NVOCAB   256
#define G4       2048   // 4*H

__device__ float g_tbl[NVOCAB * G4];      // 2 MB
__device__ float g_H0[BT_TOTAL * HDIM];   // 8 MB
__device__ float g_H1[BT_TOTAL * HDIM];   // 8 MB
__device__ float g_C [BT_TOTAL * HDIM];   // 8 MB

__device__ __forceinline__ float sigf(float x) {
    return 1.0f / (1.0f + __expf(-x));
}

// ---------------------------------------------------------------------------
// Kernel 1: precompute tbl[v,n] = dot(emb[v,:], W_ih[n,:]) + b_ih[n] + b_hh[n]
// grid (G4/128, NVOCAB), block 128
// ---------------------------------------------------------------------------
__global__ void table_kernel(const float* __restrict__ emb,
                             const float* __restrict__ W_ih,
                             const float* __restrict__ b_ih,
                             const float* __restrict__ b_hh) {
    __shared__ __align__(16) float e[EDIM];
    int v = blockIdx.y;
    for (int i = threadIdx.x; i < EDIM; i += blockDim.x)
        e[i] = emb[v * EDIM + i];
    __syncthreads();

    int n = blockIdx.x * blockDim.x + threadIdx.x;
    const float4* w4 = (const float4*)(W_ih + n * EDIM);
    const float4* e4 = (const float4*)e;
    float s = b_ih[n] + b_hh[n];
#pragma unroll 8
    for (int k = 0; k < EDIM / 4; k++) {
        float4 wv = w4[k];
        float4 ev = e4[k];
        s += ev.x * wv.x + ev.y * wv.y + ev.z * wv.z + ev.w * wv.w;
    }
    g_tbl[v * G4 + n] = s;
}

// ---------------------------------------------------------------------------
// Kernel 2: step 0 (h = c = 0). lens >= 1 always, so mask is always active.
//   c = sigmoid(i) * tanh(g);  h = sigmoid(o) * tanh(c)
// grid (BT_TOTAL, HDIM/128), block 128
// ---------------------------------------------------------------------------
__global__ void step0_kernel(const int* __restrict__ seq) {
    int m  = blockIdx.x;
    int hc = blockIdx.y * blockDim.x + threadIdx.x;
    int id = seq[m * SEQ_L];  // column t=0
    const float* tr = g_tbl + id * G4;
    float ig = sigf(tr[hc]);
    float gg = tanhf(tr[2 * HDIM + hc]);
    float og = sigf(tr[3 * HDIM + hc]);
    float cn = ig * gg;
    float hn = og * tanhf(cn);
    g_H0[m * HDIM + hc] = hn;
    g_C [m * HDIM + hc] = cn;
}

// ---------------------------------------------------------------------------
// Kernel 3: recurrent step t (1..15), fused GEMM + LSTM epilogue.
// gates[m, g*512+hc] = sum_k Hin[m,k] * W_hh[g*512+hc, k]   (NT GEMM)
// CTA tile: BM=64 rows x BN=64 h-cols x 4 gates, BK=16.
// 256 threads, each computes 4x4 per gate (64 accumulators).
// ---------------------------------------------------------------------------
#define BM 64
#define BN 64
#define BK 16

__global__ __launch_bounds__(256, 2)
void lstm_step_kernel(const float* __restrict__ W_hh,
                      const int*   __restrict__ seq,
                      const int*   __restrict__ lens,
                      float*       __restrict__ out_final,
                      int t) {
    const float* Hin  = ((t - 1) & 1) ? g_H1 : g_H0;
    float*       Hout = out_final ? out_final : ((t & 1) ? g_H1 : g_H0);

    __shared__ __align__(16) float As[BK][BM];          // 4 KB
    __shared__ __align__(16) float Bs[4][BK][BN];       // 16 KB

    const int tid = threadIdx.x;
    const int tx  = tid & 15;    // -> h-col group
    const int ty  = tid >> 4;    // -> row group
    const int m0  = blockIdx.y * BM;
    const int n0  = blockIdx.x * BN;

    float acc[4][4][4];
#pragma unroll
    for (int g = 0; g < 4; g++)
#pragma unroll
        for (int i = 0; i < 4; i++)
#pragma unroll
            for (int j = 0; j < 4; j++)
                acc[g][i][j] = 0.0f;

    const int lrow = tid >> 2;         // 0..63
    const int lk   = (tid & 3) * 4;    // 0,4,8,12

    const float* Ap = Hin + (m0 + lrow) * HDIM + lk;

    for (int k0 = 0; k0 < HDIM; k0 += BK) {
        // load A tile (64 x 16) transposed into smem
        float4 av = *(const float4*)(Ap + k0);
        As[lk + 0][lrow] = av.x;
        As[lk + 1][lrow] = av.y;
        As[lk + 2][lrow] = av.z;
        As[lk + 3][lrow] = av.w;
        // load B tiles for 4 gates (each 64 x 16) transposed into smem
#pragma unroll
        for (int g = 0; g < 4; g++) {
            float4 bv = *(const float4*)(W_hh + (g * HDIM + n0 + lrow) * HDIM + k0 + lk);
            Bs[g][lk + 0][lrow] = bv.x;
            Bs[g][lk + 1][lrow] = bv.y;
            Bs[g][lk + 2][lrow] = bv.z;
            Bs[g][lk + 3][lrow] = bv.w;
        }
        __syncthreads();

#pragma unroll
        for (int kk = 0; kk < BK; kk++) {
            float4 a4 = *(const float4*)&As[kk][ty * 4];
            float ar[4] = {a4.x, a4.y, a4.z, a4.w};
#pragma unroll
            for (int g = 0; g < 4; g++) {
                float4 b4 = *(const float4*)&Bs[g][kk][tx * 4];
                float br[4] = {b4.x, b4.y, b4.z, b4.w};
#pragma unroll
                for (int i = 0; i < 4; i++)
#pragma unroll
                    for (int j = 0; j < 4; j++)
                        acc[g][i][j] += ar[i] * br[j];
            }
        }
        __syncthreads();
    }

    // ---- fused LSTM epilogue ----
#pragma unroll
    for (int i = 0; i < 4; i++) {
        const int m  = m0 + ty * 4 + i;
        const int id = seq[m * SEQ_L + t];
        const bool act = lens[m] > t;
        const float* tr = g_tbl + id * G4;
#pragma unroll
        for (int j = 0; j < 4; j++) {
            const int hc = n0 + tx * 4 + j;
            float pi = acc[0][i][j] + tr[hc];
            float pf = acc[1][i][j] + tr[HDIM + hc];
            float pg = acc[2][i][j] + tr[2 * HDIM + hc];
            float po = acc[3][i][j] + tr[3 * HDIM + hc];
            float ig = sigf(pi);
            float fg = sigf(pf);
            float gg = tanhf(pg);
            float og = sigf(po);
            float cp = g_C[m * HDIM + hc];
            float cn = fg * cp + ig * gg;
            float hn = og * tanhf(cn);
            if (!act) {            // sequence already finished: freeze state
                hn = Hin[m * HDIM + hc];
                cn = cp;
            }
            Hout[m * HDIM + hc] = hn;
            g_C [m * HDIM + hc] = cn;
        }
    }
}

// ---------------------------------------------------------------------------
// Host entry point
// Inputs (metadata order): char_seq_padded(i32), char_lengths(i32), emb(f32),
//                          W_ih(f32), W_hh(f32), b_ih(f32), b_hh(f32)
// Output: float[B*T*H] — exactly the final h state, row-major [BT, H].
// ---------------------------------------------------------------------------
extern "C" void kernel_launch(void* const* d_in, const int* in_sizes, int n_in,
                              void* d_out, int out_size) {
    const int*   seq  = (const int*)  d_in[0];
    const int*   lens = (const int*)  d_in[1];
    const float* emb  = (const float*)d_in[2];
    const float* W_ih = (const float*)d_in[3];
    const float* W_hh = (const float*)d_in[4];
    const float* b_ih = (const float*)d_in[5];
    const float* b_hh = (const float*)d_in[6];
    float* out = (float*)d_out;

    // 1. input-projection lookup table (256 rows only)
    table_kernel<<<dim3(G4 / 128, NVOCAB), 128>>>(emb, W_ih, b_ih, b_hh);

    // 2. step 0 (h = 0): elementwise
    step0_kernel<<<dim3(BT_TOTAL, HDIM / 128), 128>>>(seq);

    // 3. steps 1..15: recurrent GEMM + fused epilogue
    for (int t = 1; t < SEQ_L; t++) {
        float* ovr = (t == SEQ_L - 1) ? out : nullptr;
        lstm_step_kernel<<<dim3(HDIM / BN, BT_TOTAL / BM), 256>>>(
            W_hh, seq, lens, ovr, t);
    }
}

// round 7
// speedup vs baseline: 2.1731x; 2.1731x over previous
#include <cuda_runtime.h>
#include <cuda_fp16.h>
#include <cstdint>

// ===========================================================================
// CharLSTMEmbedding: B=32, T=128, L=16, VOCAB=256, E=256, H=512
// sm_103 (plain target: no tcgen05) -> classic mma.sync.m16n8k16 HMMA path.
//
//  prep_w  : split W_hh into fp16 hi/lo, permute rows to n' = blk*32+g*8+hcl
//  prep_tbl: tbl[v, n'] = emb[v]·W_ih + b_ih + b_hh   (fp32, same permutation)
//  step0   : h=c=0 elementwise from tbl; h written as fp16 hi/lo split
//  lstm_step x15: gates = Hsplit @ Wsplit^T via 3-term fp16 mma.sync
//                 (Ahi*Bhi + Ahi*Blo + Alo*Bhi, fp32 accum), fused epilogue.
// ===========================================================================

#define BT   4096
#define SL   16
#define HD   512
#define ED   256
#define NV   256
#define G4   2048

__device__ __align__(256) __half g_Whi[G4 * HD];
__device__ __align__(256) __half g_Wlo[G4 * HD];
__device__ __align__(256) float  g_tbl[NV * G4];
__device__ __align__(256) __half g_Hhi[2][BT * HD];
__device__ __align__(256) __half g_Hlo[2][BT * HD];
__device__ __align__(256) float  g_C[BT * HD];

// ------------------------------ helpers -----------------------------------

__device__ __forceinline__ uint32_t smem_u32(const void* p) {
    uint32_t a;
    asm("{ .reg .u64 t; cvta.to.shared.u64 t, %1; cvt.u32.u64 %0, t; }"
        : "=r"(a) : "l"(p));
    return a;
}

__device__ __forceinline__ void cp16(uint32_t dst, const void* src) {
    asm volatile("cp.async.cg.shared.global [%0], [%1], 16;"
                 :: "r"(dst), "l"(src) : "memory");
}

__device__ __forceinline__ void ldsm4(uint32_t* r, uint32_t addr) {
    asm volatile("ldmatrix.sync.aligned.m8n8.x4.shared.b16 {%0,%1,%2,%3}, [%4];"
                 : "=r"(r[0]), "=r"(r[1]), "=r"(r[2]), "=r"(r[3]) : "r"(addr));
}
__device__ __forceinline__ void ldsm2(uint32_t* r, uint32_t addr) {
    asm volatile("ldmatrix.sync.aligned.m8n8.x2.shared.b16 {%0,%1}, [%2];"
                 : "=r"(r[0]), "=r"(r[1]) : "r"(addr));
}

__device__ __forceinline__ void mma16816(float* d, const uint32_t* a,
                                         const uint32_t* b) {
    asm volatile(
        "mma.sync.aligned.m16n8k16.row.col.f32.f16.f16.f32 "
        "{%0,%1,%2,%3}, {%4,%5,%6,%7}, {%8,%9}, {%0,%1,%2,%3};"
        : "+f"(d[0]), "+f"(d[1]), "+f"(d[2]), "+f"(d[3])
        : "r"(a[0]), "r"(a[1]), "r"(a[2]), "r"(a[3]), "r"(b[0]), "r"(b[1]));
}

__device__ __forceinline__ float sigf(float x) {
    return __fdividef(1.0f, 1.0f + __expf(-x));
}
__device__ __forceinline__ float tanhfast(float x) {
    return __fdividef(2.0f, 1.0f + __expf(-2.0f * x)) - 1.0f;
}

// permutation: n' = (hc>>3)*32 + g*8 + (hc&7)
// inverse: hc = (np>>5)*8 + (np&7); g = (np>>3)&3

// ------------------------------ prep kernels ------------------------------

__global__ void prep_w(const float* __restrict__ W) {
    int idx = blockIdx.x * 256 + threadIdx.x;          // < G4*HD
    int np = idx >> 9, k = idx & 511;
    int hc = ((np >> 5) << 3) + (np & 7);
    int g  = (np >> 3) & 3;
    float v = W[(g * HD + hc) * HD + k];
    __half hi = __float2half_rn(v);
    g_Whi[idx] = hi;
    g_Wlo[idx] = __float2half_rn(v - __half2float(hi));
}

__global__ void prep_tbl(const float* __restrict__ emb,
                         const float* __restrict__ Wih,
                         const float* __restrict__ bi,
                         const float* __restrict__ bh) {
    __shared__ __align__(16) float e[ED];
    int v = blockIdx.y;
    for (int i = threadIdx.x; i < ED; i += blockDim.x)
        e[i] = emb[v * ED + i];
    __syncthreads();

    int np = blockIdx.x * 128 + threadIdx.x;
    int hc = ((np >> 5) << 3) + (np & 7);
    int g  = (np >> 3) & 3;
    int n  = g * HD + hc;
    const float4* w4 = (const float4*)(Wih + n * ED);
    const float4* e4 = (const float4*)e;
    float s = bi[n] + bh[n];
#pragma unroll 8
    for (int k = 0; k < ED / 4; k++) {
        float4 wv = w4[k];
        float4 ev = e4[k];
        s += ev.x * wv.x + ev.y * wv.y + ev.z * wv.z + ev.w * wv.w;
    }
    g_tbl[v * G4 + np] = s;
}

__global__ void step0(const int* __restrict__ seq) {
    int m  = blockIdx.x;
    int hc = blockIdx.y * 128 + threadIdx.x;
    int id = seq[m * SL];
    int base = ((hc >> 3) << 5) + (hc & 7);            // gate stride 8
    const float* tr = g_tbl + id * G4;
    float cn = sigf(tr[base]) * tanhfast(tr[base + 16]);
    float hn = sigf(tr[base + 24]) * tanhfast(cn);
    __half hi = __float2half_rn(hn);
    g_Hhi[0][m * HD + hc] = hi;
    g_Hlo[0][m * HD + hc] = __float2half_rn(hn - __half2float(hi));
    g_C[m * HD + hc] = cn;
}

// --------------------------- recurrent step -------------------------------
// CTA tile 128(m) x 128(n'), 256 threads, 8 warps (2m x 4n), warp 64x32.
// K chunked by 64 halves, double-buffered cp.async, padded smem rows (144B).

#define ROWB    144          // 64 halves (128B) + 16B pad
#define OFF_ALO 18432        // 128*144
#define OFF_BHI 36864
#define OFF_BLO 55296
#define STG     73728
#define SMEM_TOTAL 147456

__global__ void __launch_bounds__(256, 1)
lstm_step(const int* __restrict__ seq, const int* __restrict__ lens,
          float* __restrict__ out_f, int t) {
    extern __shared__ char smem[];
    const uint32_t sb = smem_u32(smem);
    const int tid = threadIdx.x, lid = tid & 31;
    const int wm = (tid >> 5) >> 2;            // 0..1
    const int wn = (tid >> 5) & 3;             // 0..3
    const int n0 = blockIdx.x * 128, m0 = blockIdx.y * 128;

    const __half* __restrict__ Hhi_in = g_Hhi[(t + 1) & 1];
    const __half* __restrict__ Hlo_in = g_Hlo[(t + 1) & 1];
    __half* __restrict__ Hhi_out = g_Hhi[t & 1];
    __half* __restrict__ Hlo_out = g_Hlo[t & 1];

    float acc[4][4][4];
#pragma unroll
    for (int a = 0; a < 4; a++)
#pragma unroll
        for (int b = 0; b < 4; b++)
#pragma unroll
            for (int c = 0; c < 4; c++) acc[a][b][c] = 0.0f;

    // loader indices: 4 iters -> 128 rows x 8 segs of 16B
    const int lrow = tid >> 3;           // +it*32
    const int lseg = tid & 7;

    auto issue_chunk = [&](int ck, int buf) {
        const uint32_t st = sb + (uint32_t)buf * STG;
        const int k0 = ck * 64;
#pragma unroll
        for (int it = 0; it < 4; it++) {
            int r = it * 32 + lrow;
            uint32_t so = (uint32_t)(r * ROWB + lseg * 16);
            const __half* sA = Hhi_in + (m0 + r) * HD + k0 + lseg * 8;
            const __half* sAl = Hlo_in + (m0 + r) * HD + k0 + lseg * 8;
            cp16(st + so, sA);
            cp16(st + OFF_ALO + so, sAl);
            cp16(st + OFF_BHI + so, g_Whi + (n0 + r) * HD + k0 + lseg * 8);
            cp16(st + OFF_BLO + so, g_Wlo + (n0 + r) * HD + k0 + lseg * 8);
        }
        asm volatile("cp.async.commit_group;" ::: "memory");
    };

    issue_chunk(0, 0);

    // per-lane ldmatrix address components
    const uint32_t aoff = (uint32_t)((wm * 64 + (lid & 15)) * ROWB + (lid >> 4) * 16);
    const uint32_t boff = (uint32_t)((wn * 32 + (lid & 7)) * ROWB + ((lid >> 3) & 1) * 16);

    for (int ck = 0; ck < 8; ck++) {
        if (ck < 7) {
            issue_chunk(ck + 1, (ck + 1) & 1);
            asm volatile("cp.async.wait_group 1;" ::: "memory");
        } else {
            asm volatile("cp.async.wait_group 0;" ::: "memory");
        }
        __syncthreads();

        const uint32_t st = sb + (uint32_t)(ck & 1) * STG;
        const uint32_t aHi = st + aoff;
        const uint32_t aLo = st + OFF_ALO + aoff;
        const uint32_t bHi = st + OFF_BHI + boff;
        const uint32_t bLo = st + OFF_BLO + boff;

#pragma unroll
        for (int k16 = 0; k16 < 4; k16++) {
            const uint32_t kb = (uint32_t)(k16 * 32);
            uint32_t ah[4][4], al[4][4], bh[4][2], bl[4][2];
#pragma unroll
            for (int mt = 0; mt < 4; mt++) {
                ldsm4(ah[mt], aHi + (uint32_t)(mt * 16 * ROWB) + kb);
                ldsm4(al[mt], aLo + (uint32_t)(mt * 16 * ROWB) + kb);
            }
#pragma unroll
            for (int g = 0; g < 4; g++) {
                ldsm2(bh[g], bHi + (uint32_t)(g * 8 * ROWB) + kb);
                ldsm2(bl[g], bLo + (uint32_t)(g * 8 * ROWB) + kb);
            }
#pragma unroll
            for (int mt = 0; mt < 4; mt++)
#pragma unroll
                for (int g = 0; g < 4; g++) {
                    mma16816(acc[mt][g], ah[mt], bh[g]);
                    mma16816(acc[mt][g], ah[mt], bl[g]);
                    mma16816(acc[mt][g], al[mt], bh[g]);
                }
        }
        __syncthreads();
    }

    // ---------------- fused LSTM epilogue ----------------
    // thread lane: q = lid&3 -> hcl pair (2q, 2q+1); r = lid>>2 (rows r, r+8)
    const int q = lid & 3, r = lid >> 2;
    const int cn0 = n0 + wn * 32;
    const int hcb = (cn0 >> 2) + 2 * q;        // global hc of pair start
    const bool fin = (out_f != nullptr);

#pragma unroll
    for (int mt = 0; mt < 4; mt++) {
#pragma unroll
        for (int v = 0; v < 2; v++) {
            const int m = m0 + wm * 64 + mt * 16 + r + v * 8;
            const int id = seq[m * SL + t];
            const bool act = lens[m] > t;
            if (act) {
                const float* tr = g_tbl + id * G4 + cn0 + 2 * q;
                float2 cp = *(const float2*)(g_C + m * HD + hcb);
                float co[2] = {cp.x, cp.y};
                float h2[2], c2[2];
#pragma unroll
                for (int j = 0; j < 2; j++) {
                    float pi = acc[mt][0][2 * v + j] + tr[0 + j];
                    float pf = acc[mt][1][2 * v + j] + tr[8 + j];
                    float pg = acc[mt][2][2 * v + j] + tr[16 + j];
                    float po = acc[mt][3][2 * v + j] + tr[24 + j];
                    float ig = sigf(pi), fg = sigf(pf);
                    float gg = tanhfast(pg), og = sigf(po);
                    float cc = fg * co[j] + ig * gg;
                    c2[j] = cc;
                    h2[j] = og * tanhfast(cc);
                }
                *(float2*)(g_C + m * HD + hcb) = make_float2(c2[0], c2[1]);
                __half hi0 = __float2half_rn(h2[0]);
                __half hi1 = __float2half_rn(h2[1]);
                __half lo0 = __float2half_rn(h2[0] - __half2float(hi0));
                __half lo1 = __float2half_rn(h2[1] - __half2float(hi1));
                *(__half2*)(Hhi_out + m * HD + hcb) = __halves2half2(hi0, hi1);
                *(__half2*)(Hlo_out + m * HD + hcb) = __halves2half2(lo0, lo1);
                if (fin)
                    *(float2*)(out_f + m * HD + hcb) = make_float2(h2[0], h2[1]);
            } else {
                __half2 vh = *(const __half2*)(Hhi_in + m * HD + hcb);
                __half2 vl = *(const __half2*)(Hlo_in + m * HD + hcb);
                *(__half2*)(Hhi_out + m * HD + hcb) = vh;
                *(__half2*)(Hlo_out + m * HD + hcb) = vl;
                if (fin) {
                    float2 fh = __half22float2(vh);
                    float2 fl = __half22float2(vl);
                    *(float2*)(out_f + m * HD + hcb) =
                        make_float2(fh.x + fl.x, fh.y + fl.y);
                }
            }
        }
    }
}

// ------------------------------ host entry --------------------------------
// Inputs: char_seq_padded(i32), char_lengths(i32), emb, W_ih, W_hh, b_ih, b_hh
extern "C" void kernel_launch(void* const* d_in, const int* in_sizes, int n_in,
                              void* d_out, int out_size) {
    const int*   seq  = (const int*)  d_in[0];
    const int*   lens = (const int*)  d_in[1];
    const float* emb  = (const float*)d_in[2];
    const float* W_ih = (const float*)d_in[3];
    const float* W_hh = (const float*)d_in[4];
    const float* b_ih = (const float*)d_in[5];
    const float* b_hh = (const float*)d_in[6];
    float* out = (float*)d_out;

    cudaFuncSetAttribute(lstm_step,
                         cudaFuncAttributeMaxDynamicSharedMemorySize,
                         SMEM_TOTAL);

    prep_w<<<(G4 * HD) / 256, 256>>>(W_hh);
    prep_tbl<<<dim3(G4 / 128, NV), 128>>>(emb, W_ih, b_ih, b_hh);
    step0<<<dim3(BT, HD / 128), 128>>>(seq);

    for (int t = 1; t < SL; t++) {
        float* o = (t == SL - 1) ? out : nullptr;
        lstm_step<<<dim3(G4 / 128, BT / 128), 256, SMEM_TOTAL>>>(seq, lens, o, t);
    }
}

// round 8
// speedup vs baseline: 2.7077x; 1.2460x over previous
#include <cuda_runtime.h>
#include <cuda_fp16.h>
#include <cstdint>

// ===========================================================================
// CharLSTMEmbedding: B=32, T=128, L=16, VOCAB=256, E=256, H=512
// sm_103 plain target -> mma.sync HMMA + cp.async.bulk (UBLKCP) loads.
//
// Key change vs R7: H-state and W are stored in GLOBAL memory already in the
// tile-major, SW128-swizzled layout the smem consumer wants. Each K-chunk is
// then fetched with TWO cp.async.bulk instructions (32KB each) instead of
// 4096 LDGSTS ops (whose 8cyc/op issue cost was the R7 bottleneck).
//
// Layouts:
//   g_W[ntile(16)][ck(8)][hi 16KB | lo 16KB]   tile = 128 rows x 64 halves SW128
//   g_A[buf(2)][mtile(32)][ck(8)][hi | lo]     same tile format (h state)
//   n' permutation: n' = (hc>>3)*32 + g*8 + (hc&7)  (epilogue shuffle-free)
// ===========================================================================

#define BT   4096
#define SL   16
#define HD   512
#define ED   256
#define NV   256
#define G4   2048

#define TILEB 16384            // 128 x 64 halves, swizzled
#define CKB   32768            // hi + lo tile pair

__device__ __align__(1024) unsigned char g_W[16 * 8 * CKB];       // 4 MB
__device__ __align__(1024) unsigned char g_A[2][32 * 8 * CKB];    // 2 x 8 MB
__device__ __align__(256) float g_tbl[NV * G4];                   // 2 MB
__device__ __align__(256) float g_C[BT * HD];                     // 8 MB

// ------------------------------ helpers -----------------------------------

__device__ __forceinline__ uint32_t smem_u32(const void* p) {
    uint32_t a;
    asm("{ .reg .u64 t; cvta.to.shared.u64 t, %1; cvt.u32.u64 %0, t; }"
        : "=r"(a) : "l"(p));
    return a;
}

// byte offset inside one 128x64-half tile, SW128: x ^= (row&7)<<4
__device__ __forceinline__ uint32_t tswz(uint32_t row, uint32_t x) {
    return row * 128u + (x ^ ((row & 7u) << 4));
}

__device__ __forceinline__ void bulk_cp(uint32_t dst, const void* src,
                                        uint32_t bytes, uint32_t mbar) {
    asm volatile(
        "cp.async.bulk.shared::cluster.global.mbarrier::complete_tx::bytes "
        "[%0], [%1], %2, [%3];"
        :: "r"(dst), "l"(src), "r"(bytes), "r"(mbar) : "memory");
}

__device__ __forceinline__ void mbar_init(uint32_t mbar, uint32_t cnt) {
    asm volatile("mbarrier.init.shared.b64 [%0], %1;" :: "r"(mbar), "r"(cnt)
                 : "memory");
}
__device__ __forceinline__ void mbar_expect(uint32_t mbar, uint32_t bytes) {
    asm volatile("mbarrier.arrive.expect_tx.shared.b64 _, [%0], %1;"
                 :: "r"(mbar), "r"(bytes) : "memory");
}
__device__ __forceinline__ void mbar_wait(uint32_t mbar, uint32_t parity) {
    asm volatile(
        "{\n\t.reg .pred P;\n\t"
        "WL_%=:\n\t"
        "mbarrier.try_wait.parity.acquire.cta.shared::cta.b64 P, [%0], %1, 0x989680;\n\t"
        "@P bra.uni WD_%=;\n\t"
        "bra.uni WL_%=;\n\t"
        "WD_%=:\n\t}"
        :: "r"(mbar), "r"(parity) : "memory");
}

__device__ __forceinline__ void ldsm4(uint32_t* r, uint32_t addr) {
    asm volatile("ldmatrix.sync.aligned.m8n8.x4.shared.b16 {%0,%1,%2,%3}, [%4];"
                 : "=r"(r[0]), "=r"(r[1]), "=r"(r[2]), "=r"(r[3]) : "r"(addr));
}
__device__ __forceinline__ void ldsm2(uint32_t* r, uint32_t addr) {
    asm volatile("ldmatrix.sync.aligned.m8n8.x2.shared.b16 {%0,%1}, [%2];"
                 : "=r"(r[0]), "=r"(r[1]) : "r"(addr));
}

__device__ __forceinline__ void mma16816(float* d, const uint32_t* a,
                                         const uint32_t* b) {
    asm volatile(
        "mma.sync.aligned.m16n8k16.row.col.f32.f16.f16.f32 "
        "{%0,%1,%2,%3}, {%4,%5,%6,%7}, {%8,%9}, {%0,%1,%2,%3};"
        : "+f"(d[0]), "+f"(d[1]), "+f"(d[2]), "+f"(d[3])
        : "r"(a[0]), "r"(a[1]), "r"(a[2]), "r"(a[3]), "r"(b[0]), "r"(b[1]));
}

__device__ __forceinline__ float sigf(float x) {
    return __fdividef(1.0f, 1.0f + __expf(-x));
}
__device__ __forceinline__ float tanhfast(float x) {
    return __fdividef(2.0f, 1.0f + __expf(-2.0f * x)) - 1.0f;
}

// permutation n' = (hc>>3)*32 + g*8 + (hc&7);  inverse:
//   hc = (np>>5)*8 + (np&7);  g = (np>>3)&3

// ------------------------------ prep kernels ------------------------------

// Split+permute W_hh into packed swizzled tiles.
__global__ void prep_w(const float* __restrict__ W) {
    int idx = blockIdx.x * 256 + threadIdx.x;      // < G4*HD
    int np = idx >> 9, k = idx & 511;
    int hc = ((np >> 5) << 3) + (np & 7);
    int g  = (np >> 3) & 3;
    float v = W[(g * HD + hc) * HD + k];
    __half hi = __float2half_rn(v);
    __half lo = __float2half_rn(v - __half2float(hi));
    uint32_t base = (uint32_t)((np >> 7) * 8 + (k >> 6)) * CKB;
    uint32_t off  = tswz((uint32_t)(np & 127), (uint32_t)((k & 63) * 2));
    *(__half*)(g_W + base + off)         = hi;
    *(__half*)(g_W + base + TILEB + off) = lo;
}

__global__ void prep_tbl(const float* __restrict__ emb,
                         const float* __restrict__ Wih,
                         const float* __restrict__ bi,
                         const float* __restrict__ bh) {
    __shared__ __align__(16) float e[ED];
    int v = blockIdx.y;
    for (int i = threadIdx.x; i < ED; i += blockDim.x)
        e[i] = emb[v * ED + i];
    __syncthreads();

    int np = blockIdx.x * 128 + threadIdx.x;
    int hc = ((np >> 5) << 3) + (np & 7);
    int g  = (np >> 3) & 3;
    int n  = g * HD + hc;
    const float4* w4 = (const float4*)(Wih + n * ED);
    const float4* e4 = (const float4*)e;
    float s = bi[n] + bh[n];
#pragma unroll 8
    for (int k = 0; k < ED / 4; k++) {
        float4 wv = w4[k];
        float4 ev = e4[k];
        s += ev.x * wv.x + ev.y * wv.y + ev.z * wv.z + ev.w * wv.w;
    }
    g_tbl[v * G4 + np] = s;
}

// step 0: h = c = 0 (lens >= 1 always active); write h into packed A buf 0
__global__ void step0(const int* __restrict__ seq) {
    int m  = blockIdx.x;
    int hc = blockIdx.y * 128 + threadIdx.x;
    int id = seq[m * SL];
    int base = ((hc >> 3) << 5) + (hc & 7);        // gate stride 8 in tbl
    const float* tr = g_tbl + id * G4;
    float cn = sigf(tr[base]) * tanhfast(tr[base + 16]);
    float hn = sigf(tr[base + 24]) * tanhfast(cn);
    __half hi = __float2half_rn(hn);
    __half lo = __float2half_rn(hn - __half2float(hi));
    uint32_t tb  = (uint32_t)((m >> 7) * 8 + (hc >> 6)) * CKB;
    uint32_t off = tswz((uint32_t)(m & 127), (uint32_t)((hc & 63) * 2));
    *(__half*)(g_A[0] + tb + off)         = hi;
    *(__half*)(g_A[0] + tb + TILEB + off) = lo;
    g_C[m * HD + hc] = cn;
}

// --------------------------- recurrent step -------------------------------
// CTA 128(m) x 128(n'), 256 threads, 8 warps (2m x 4n), warp 64x32.
// K in 8 chunks of 64; 3-stage bulk-copy pipeline; buffer = 64KB
// [Ahi|Alo|Bhi|Blo].

#define SMEM_TOTAL (1024 + 3 * 65536)

__global__ void __launch_bounds__(256, 1)
lstm_step(const int* __restrict__ seq, const int* __restrict__ lens,
          float* __restrict__ out_f, int t) {
    extern __shared__ char smem[];
    const uint32_t sb = smem_u32(smem);
    const int tid = threadIdx.x, lid = tid & 31;
    const int wm = (tid >> 5) >> 2;            // 0..1
    const int wn = (tid >> 5) & 3;             // 0..3

    const unsigned char* __restrict__ Asrc =
        g_A[(t + 1) & 1] + (size_t)blockIdx.y * 8 * CKB;
    const unsigned char* __restrict__ Wsrc =
        g_W + (size_t)blockIdx.x * 8 * CKB;

    if (tid == 0) {
        mbar_init(sb + 0, 1);
        mbar_init(sb + 8, 1);
        mbar_init(sb + 16, 1);
    }
    __syncthreads();

    auto issue = [&](int ck) {
        uint32_t buf = (uint32_t)(ck % 3);
        uint32_t dst = sb + 1024 + buf * 65536;
        uint32_t mb  = sb + buf * 8;
        mbar_expect(mb, 65536);
        bulk_cp(dst,         Asrc + ck * CKB, CKB, mb);   // Ahi|Alo
        bulk_cp(dst + CKB,   Wsrc + ck * CKB, CKB, mb);   // Bhi|Blo
    };
    if (tid == 0) { issue(0); issue(1); issue(2); }

    float acc[4][4][4];
#pragma unroll
    for (int a = 0; a < 4; a++)
#pragma unroll
        for (int b = 0; b < 4; b++)
#pragma unroll
            for (int c = 0; c < 4; c++) acc[a][b][c] = 0.0f;

    // per-lane ldmatrix base components (swizzle xor is row&7-invariant
    // across mt*16 / g*8 row steps)
    const uint32_t arow = (uint32_t)(wm * 64 + (lid & 15));
    const uint32_t axor = (arow & 7u) << 4;
    const uint32_t acol = (uint32_t)((lid >> 4) * 16);
    const uint32_t brow = (uint32_t)(wn * 32 + (lid & 7));
    const uint32_t bxor = (brow & 7u) << 4;
    const uint32_t bcol = (uint32_t)(((lid >> 3) & 1) * 16);

    for (int ck = 0; ck < 8; ck++) {
        const uint32_t buf = (uint32_t)(ck % 3);
        mbar_wait(sb + buf * 8, (uint32_t)((ck / 3) & 1));

        const uint32_t cb = sb + 1024 + buf * 65536;
        const uint32_t sAhi = cb, sAlo = cb + TILEB;
        const uint32_t sBhi = cb + 2 * TILEB, sBlo = cb + 3 * TILEB;

#pragma unroll
        for (int k16 = 0; k16 < 4; k16++) {
            const uint32_t ax = ((uint32_t)(k16 * 32) + acol) ^ axor;
            const uint32_t bx = ((uint32_t)(k16 * 32) + bcol) ^ bxor;
            uint32_t ah[4][4], al[4][4], bhf[4][2], blf[4][2];
#pragma unroll
            for (int mt = 0; mt < 4; mt++) {
                uint32_t ro = (arow + (uint32_t)(mt * 16)) * 128u;
                ldsm4(ah[mt], sAhi + ro + ax);
                ldsm4(al[mt], sAlo + ro + ax);
            }
#pragma unroll
            for (int g = 0; g < 4; g++) {
                uint32_t ro = (brow + (uint32_t)(g * 8)) * 128u;
                ldsm2(bhf[g], sBhi + ro + bx);
                ldsm2(blf[g], sBlo + ro + bx);
            }
#pragma unroll
            for (int mt = 0; mt < 4; mt++)
#pragma unroll
                for (int g = 0; g < 4; g++) {
                    mma16816(acc[mt][g], ah[mt], bhf[g]);
                    mma16816(acc[mt][g], ah[mt], blf[g]);
                    mma16816(acc[mt][g], al[mt], bhf[g]);
                }
        }
        __syncthreads();                 // all lanes done reading buf
        if (ck + 3 < 8 && tid == 0) issue(ck + 3);
    }

    // ---------------- fused LSTM epilogue ----------------
    const int q = lid & 3, r = lid >> 2;
    const int n0 = blockIdx.x * 128, m0 = (int)blockIdx.y * 128;
    const int cn0 = n0 + wn * 32;
    const int hcb = (cn0 >> 2) + 2 * q;            // even, pair (hcb, hcb+1)
    const bool fin = (out_f != nullptr);
    unsigned char* __restrict__ Aout = g_A[t & 1];
    const unsigned char* __restrict__ Ain = g_A[(t + 1) & 1];

    const uint32_t ckh  = (uint32_t)(hcb >> 6);
    const uint32_t xoff = (uint32_t)((hcb & 63) * 2);

#pragma unroll
    for (int mt = 0; mt < 4; mt++) {
#pragma unroll
        for (int v = 0; v < 2; v++) {
            const int m = m0 + wm * 64 + mt * 16 + r + v * 8;
            const int id = seq[m * SL + t];
            const bool act = lens[m] > t;
            const uint32_t tb  = (uint32_t)((m >> 7) * 8) * CKB + ckh * CKB;
            const uint32_t off = tswz((uint32_t)(m & 127), xoff);
            __half2* phiO = (__half2*)(Aout + tb + off);
            __half2* ploO = (__half2*)(Aout + tb + TILEB + off);
            if (act) {
                const float* tr = g_tbl + id * G4 + cn0 + 2 * q;
                float2 cp = *(const float2*)(g_C + m * HD + hcb);
                float co[2] = {cp.x, cp.y};
                float h2[2], c2[2];
#pragma unroll
                for (int j = 0; j < 2; j++) {
                    float pi = acc[mt][0][2 * v + j] + tr[0 + j];
                    float pf = acc[mt][1][2 * v + j] + tr[8 + j];
                    float pg = acc[mt][2][2 * v + j] + tr[16 + j];
                    float po = acc[mt][3][2 * v + j] + tr[24 + j];
                    float ig = sigf(pi), fg = sigf(pf);
                    float gg = tanhfast(pg), og = sigf(po);
                    float cc = fg * co[j] + ig * gg;
                    c2[j] = cc;
                    h2[j] = og * tanhfast(cc);
                }
                *(float2*)(g_C + m * HD + hcb) = make_float2(c2[0], c2[1]);
                __half hi0 = __float2half_rn(h2[0]);
                __half hi1 = __float2half_rn(h2[1]);
                __half lo0 = __float2half_rn(h2[0] - __half2float(hi0));
                __half lo1 = __float2half_rn(h2[1] - __half2float(hi1));
                *phiO = __halves2half2(hi0, hi1);
                *ploO = __halves2half2(lo0, lo1);
                if (fin)
                    *(float2*)(out_f + m * HD + hcb) = make_float2(h2[0], h2[1]);
            } else {
                __half2 vh = *(const __half2*)(Ain + tb + off);
                __half2 vl = *(const __half2*)(Ain + tb + TILEB + off);
                *phiO = vh;
                *ploO = vl;
                if (fin) {
                    float2 fh = __half22float2(vh);
                    float2 fl = __half22float2(vl);
                    *(float2*)(out_f + m * HD + hcb) =
                        make_float2(fh.x + fl.x, fh.y + fl.y);
                }
            }
        }
    }
}

// ------------------------------ host entry --------------------------------
// Inputs: char_seq_padded(i32), char_lengths(i32), emb, W_ih, W_hh, b_ih, b_hh
extern "C" void kernel_launch(void* const* d_in, const int* in_sizes, int n_in,
                              void* d_out, int out_size) {
    const int*   seq  = (const int*)  d_in[0];
    const int*   lens = (const int*)  d_in[1];
    const float* emb  = (const float*)d_in[2];
    const float* W_ih = (const float*)d_in[3];
    const float* W_hh = (const float*)d_in[4];
    const float* b_ih = (const float*)d_in[5];
    const float* b_hh = (const float*)d_in[6];
    float* out = (float*)d_out;

    cudaFuncSetAttribute(lstm_step,
                         cudaFuncAttributeMaxDynamicSharedMemorySize,
                         SMEM_TOTAL);

    prep_w<<<(G4 * HD) / 256, 256>>>(W_hh);
    prep_tbl<<<dim3(G4 / 128, NV), 128>>>(emb, W_ih, b_ih, b_hh);
    step0<<<dim3(BT, HD / 128), 128>>>(seq);

    for (int t = 1; t < SL; t++) {
        float* o = (t == SL - 1) ? out : nullptr;
        lstm_step<<<dim3(G4 / 128, BT / 128), 256, SMEM_TOTAL>>>(seq, lens, o, t);
    }
}

// round 9
// speedup vs baseline: 3.1847x; 1.1762x over previous
#include <cuda_runtime.h>
#include <cuda_fp16.h>
#include <cstdint>

// ===========================================================================
// CharLSTMEmbedding: B=32, T=128, L=16, VOCAB=256, E=256, H=512
// sm_103 plain target -> mma.sync HMMA + cp.async.bulk loads.
//
// R9: 2 CTAs/SM. K-chunk = 32 (stage 32KB = Ahi|Alo|Bhi|Blo @ 8KB), 3-stage
// mbarrier pipeline -> 97KB smem/CTA, launch_bounds(256,2) -> occupancy 2.
// Tiles are 128 rows x 32 halves, stored paired-row swizzled (2 rows / 128B
// line) in GLOBAL memory so each chunk is two 16KB bulk copies.
//
//   swz: off(r,x) = (r>>1)*128 + (((r&1)*64 + x) ^ (((r>>1)&7)<<4))
//   n' permutation: n' = (hc>>3)*32 + g*8 + (hc&7)   (epilogue shuffle-free)
// ===========================================================================

#define BT   4096
#define SL   16
#define HD   512
#define ED   256
#define NV   256
#define G4   2048

#define TIL  8192              // one 128x32-half tile (hi or lo)
#define CK2  16384             // hi+lo pair
#define NCK  16                // K chunks of 32

__device__ __align__(1024) unsigned char g_W[16 * NCK * CK2];     // 4 MB
__device__ __align__(1024) unsigned char g_A[2][32 * NCK * CK2];  // 2 x 8 MB
__device__ __align__(256) float g_tbl[NV * G4];                   // 2 MB
__device__ __align__(256) float g_C[BT * HD];                     // 8 MB

// ------------------------------ helpers -----------------------------------

__device__ __forceinline__ uint32_t smem_u32(const void* p) {
    uint32_t a;
    asm("{ .reg .u64 t; cvta.to.shared.u64 t, %1; cvt.u32.u64 %0, t; }"
        : "=r"(a) : "l"(p));
    return a;
}

// paired-row swizzle for 128row x 64B tiles
__device__ __forceinline__ uint32_t swz32(uint32_t r, uint32_t x) {
    return (r >> 1) * 128u + ((((r & 1u) << 6) + x) ^ ((r & 14u) << 3));
}

__device__ __forceinline__ void bulk_cp(uint32_t dst, const void* src,
                                        uint32_t bytes, uint32_t mbar) {
    asm volatile(
        "cp.async.bulk.shared::cluster.global.mbarrier::complete_tx::bytes "
        "[%0], [%1], %2, [%3];"
        :: "r"(dst), "l"(src), "r"(bytes), "r"(mbar) : "memory");
}

__device__ __forceinline__ void mbar_init(uint32_t mbar, uint32_t cnt) {
    asm volatile("mbarrier.init.shared.b64 [%0], %1;" :: "r"(mbar), "r"(cnt)
                 : "memory");
}
__device__ __forceinline__ void mbar_expect(uint32_t mbar, uint32_t bytes) {
    asm volatile("mbarrier.arrive.expect_tx.shared.b64 _, [%0], %1;"
                 :: "r"(mbar), "r"(bytes) : "memory");
}
__device__ __forceinline__ void mbar_wait(uint32_t mbar, uint32_t parity) {
    asm volatile(
        "{\n\t.reg .pred P;\n\t"
        "WL_%=:\n\t"
        "mbarrier.try_wait.parity.acquire.cta.shared::cta.b64 P, [%0], %1, 0x989680;\n\t"
        "@P bra.uni WD_%=;\n\t"
        "bra.uni WL_%=;\n\t"
        "WD_%=:\n\t}"
        :: "r"(mbar), "r"(parity) : "memory");
}

__device__ __forceinline__ void ldsm4(uint32_t* r, uint32_t addr) {
    asm volatile("ldmatrix.sync.aligned.m8n8.x4.shared.b16 {%0,%1,%2,%3}, [%4];"
                 : "=r"(r[0]), "=r"(r[1]), "=r"(r[2]), "=r"(r[3]) : "r"(addr));
}
__device__ __forceinline__ void ldsm2(uint32_t* r, uint32_t addr) {
    asm volatile("ldmatrix.sync.aligned.m8n8.x2.shared.b16 {%0,%1}, [%2];"
                 : "=r"(r[0]), "=r"(r[1]) : "r"(addr));
}

__device__ __forceinline__ void mma16816(float* d, const uint32_t* a,
                                         const uint32_t* b) {
    asm volatile(
        "mma.sync.aligned.m16n8k16.row.col.f32.f16.f16.f32 "
        "{%0,%1,%2,%3}, {%4,%5,%6,%7}, {%8,%9}, {%0,%1,%2,%3};"
        : "+f"(d[0]), "+f"(d[1]), "+f"(d[2]), "+f"(d[3])
        : "r"(a[0]), "r"(a[1]), "r"(a[2]), "r"(a[3]), "r"(b[0]), "r"(b[1]));
}

__device__ __forceinline__ float sigf(float x) {
    return __fdividef(1.0f, 1.0f + __expf(-x));
}
__device__ __forceinline__ float tanhfast(float x) {
    return __fdividef(2.0f, 1.0f + __expf(-2.0f * x)) - 1.0f;
}

// ------------------------------ prep kernels ------------------------------

__global__ void prep_w(const float* __restrict__ W) {
    int idx = blockIdx.x * 256 + threadIdx.x;      // < G4*HD
    int np = idx >> 9, k = idx & 511;
    int hc = ((np >> 5) << 3) + (np & 7);
    int g  = (np >> 3) & 3;
    float v = W[(g * HD + hc) * HD + k];
    __half hi = __float2half_rn(v);
    __half lo = __float2half_rn(v - __half2float(hi));
    uint32_t base = (uint32_t)((np >> 7) * NCK + (k >> 5)) * CK2;
    uint32_t off  = swz32((uint32_t)(np & 127), (uint32_t)((k & 31) * 2));
    *(__half*)(g_W + base + off)       = hi;
    *(__half*)(g_W + base + TIL + off) = lo;
}

__global__ void prep_tbl(const float* __restrict__ emb,
                         const float* __restrict__ Wih,
                         const float* __restrict__ bi,
                         const float* __restrict__ bh) {
    __shared__ __align__(16) float e[ED];
    int v = blockIdx.y;
    for (int i = threadIdx.x; i < ED; i += blockDim.x)
        e[i] = emb[v * ED + i];
    __syncthreads();

    int np = blockIdx.x * 128 + threadIdx.x;
    int hc = ((np >> 5) << 3) + (np & 7);
    int g  = (np >> 3) & 3;
    int n  = g * HD + hc;
    const float4* w4 = (const float4*)(Wih + n * ED);
    const float4* e4 = (const float4*)e;
    float s = bi[n] + bh[n];
#pragma unroll 8
    for (int k = 0; k < ED / 4; k++) {
        float4 wv = w4[k];
        float4 ev = e4[k];
        s += ev.x * wv.x + ev.y * wv.y + ev.z * wv.z + ev.w * wv.w;
    }
    g_tbl[v * G4 + np] = s;
}

// step 0: h = c = 0 (lens >= 1 always active); write h into packed A buf 0
__global__ void step0(const int* __restrict__ seq) {
    int m  = blockIdx.x;
    int hc = blockIdx.y * 128 + threadIdx.x;
    int id = seq[m * SL];
    int base = ((hc >> 3) << 5) + (hc & 7);        // gate stride 8 in tbl
    const float* tr = g_tbl + id * G4;
    float cn = sigf(tr[base]) * tanhfast(tr[base + 16]);
    float hn = sigf(tr[base + 24]) * tanhfast(cn);
    __half hi = __float2half_rn(hn);
    __half lo = __float2half_rn(hn - __half2float(hi));
    uint32_t tb  = (uint32_t)((m >> 7) * NCK + (hc >> 5)) * CK2;
    uint32_t off = swz32((uint32_t)(m & 127), (uint32_t)((hc & 31) * 2));
    *(__half*)(g_A[0] + tb + off)       = hi;
    *(__half*)(g_A[0] + tb + TIL + off) = lo;
    g_C[m * HD + hc] = cn;
}

// --------------------------- recurrent step -------------------------------
// CTA 128(m) x 128(n'), 256 threads, 8 warps (2m x 4n), warp 64x32.
// 16 K-chunks of 32, 3-stage bulk pipeline, stage 32KB.

#define SMEM_TOTAL (1024 + 3 * 32768)

__global__ void __launch_bounds__(256, 2)
lstm_step(const int* __restrict__ seq, const int* __restrict__ lens,
          float* __restrict__ out_f, int t) {
    extern __shared__ char smem[];
    const uint32_t sb = smem_u32(smem);
    const int tid = threadIdx.x, lid = tid & 31;
    const int wm = (tid >> 5) >> 2;            // 0..1
    const int wn = (tid >> 5) & 3;             // 0..3

    const unsigned char* __restrict__ Asrc =
        g_A[(t + 1) & 1] + (size_t)blockIdx.y * NCK * CK2;
    const unsigned char* __restrict__ Wsrc =
        g_W + (size_t)blockIdx.x * NCK * CK2;

    if (tid == 0) {
        mbar_init(sb + 0, 1);
        mbar_init(sb + 8, 1);
        mbar_init(sb + 16, 1);
    }
    __syncthreads();

    auto issue = [&](int ck) {
        uint32_t buf = (uint32_t)(ck % 3);
        uint32_t dst = sb + 1024 + buf * 32768;
        uint32_t mb  = sb + buf * 8;
        mbar_expect(mb, 32768);
        bulk_cp(dst,         Asrc + ck * CK2, CK2, mb);   // Ahi|Alo
        bulk_cp(dst + CK2,   Wsrc + ck * CK2, CK2, mb);   // Bhi|Blo
    };
    if (tid == 0) { issue(0); issue(1); issue(2); }

    float acc[4][4][4];
#pragma unroll
    for (int a = 0; a < 4; a++)
#pragma unroll
        for (int b = 0; b < 4; b++)
#pragma unroll
            for (int c = 0; c < 4; c++) acc[a][b][c] = 0.0f;

    const uint32_t arow = (uint32_t)(wm * 64 + (lid & 15));
    const uint32_t acs  = (uint32_t)((lid >> 4) * 16);        // A k-seg
    const uint32_t brow = (uint32_t)(wn * 32 + (lid & 7));
    const uint32_t bcs  = (uint32_t)(((lid >> 3) & 1) * 16);  // B k-seg

    for (int ck = 0; ck < NCK; ck++) {
        const uint32_t buf = (uint32_t)(ck % 3);
        mbar_wait(sb + buf * 8, (uint32_t)((ck / 3) & 1));

        const uint32_t cb = sb + 1024 + buf * 32768;
        const uint32_t sAhi = cb, sAlo = cb + TIL;
        const uint32_t sBhi = cb + 2 * TIL, sBlo = cb + 3 * TIL;

#pragma unroll
        for (int k16 = 0; k16 < 2; k16++) {
            const uint32_t ax = (uint32_t)(k16 * 32) + acs;
            const uint32_t bx = (uint32_t)(k16 * 32) + bcs;
            // B fragments first (32 regs), A per-mt (8 regs live)
            uint32_t bhf[4][2], blf[4][2];
#pragma unroll
            for (int g = 0; g < 4; g++) {
                uint32_t ro = swz32(brow + (uint32_t)(g * 8), bx);
                ldsm2(bhf[g], sBhi + ro);
                ldsm2(blf[g], sBlo + ro);
            }
#pragma unroll
            for (int mt = 0; mt < 4; mt++) {
                uint32_t ro = swz32(arow + (uint32_t)(mt * 16), ax);
                uint32_t ah[4], al[4];
                ldsm4(ah, sAhi + ro);
                ldsm4(al, sAlo + ro);
#pragma unroll
                for (int g = 0; g < 4; g++) {
                    mma16816(acc[mt][g], ah, bhf[g]);
                    mma16816(acc[mt][g], ah, blf[g]);
                    mma16816(acc[mt][g], al, bhf[g]);
                }
            }
        }
        __syncthreads();                 // all warps done reading buf
        if (ck + 3 < NCK && tid == 0) issue(ck + 3);
    }

    // ---------------- fused LSTM epilogue ----------------
    const int q = lid & 3, r = lid >> 2;
    const int n0 = blockIdx.x * 128, m0 = (int)blockIdx.y * 128;
    const int cn0 = n0 + wn * 32;
    const int hcb = (cn0 >> 2) + 2 * q;            // even, pair (hcb, hcb+1)
    const bool fin = (out_f != nullptr);
    unsigned char* __restrict__ Aout = g_A[t & 1];
    const unsigned char* __restrict__ Ain = g_A[(t + 1) & 1];

    const uint32_t ckh  = (uint32_t)(hcb >> 5);
    const uint32_t xoff = (uint32_t)((hcb & 31) * 2);

#pragma unroll
    for (int mt = 0; mt < 4; mt++) {
#pragma unroll
        for (int v = 0; v < 2; v++) {
            const int m = m0 + wm * 64 + mt * 16 + r + v * 8;
            const int id = seq[m * SL + t];
            const bool act = lens[m] > t;
            const uint32_t tb  = ((uint32_t)(m >> 7) * NCK + ckh) * CK2;
            const uint32_t off = swz32((uint32_t)(m & 127), xoff);
            __half2* phiO = (__half2*)(Aout + tb + off);
            __half2* ploO = (__half2*)(Aout + tb + TIL + off);
            if (act) {
                const float* tr = g_tbl + id * G4 + cn0 + 2 * q;
                float2 cp = *(const float2*)(g_C + m * HD + hcb);
                float co[2] = {cp.x, cp.y};
                float h2[2], c2[2];
#pragma unroll
                for (int j = 0; j < 2; j++) {
                    float pi = acc[mt][0][2 * v + j] + tr[0 + j];
                    float pf = acc[mt][1][2 * v + j] + tr[8 + j];
                    float pg = acc[mt][2][2 * v + j] + tr[16 + j];
                    float po = acc[mt][3][2 * v + j] + tr[24 + j];
                    float ig = sigf(pi), fg = sigf(pf);
                    float gg = tanhfast(pg), og = sigf(po);
                    float cc = fg * co[j] + ig * gg;
                    c2[j] = cc;
                    h2[j] = og * tanhfast(cc);
                }
                *(float2*)(g_C + m * HD + hcb) = make_float2(c2[0], c2[1]);
                __half hi0 = __float2half_rn(h2[0]);
                __half hi1 = __float2half_rn(h2[1]);
                __half lo0 = __float2half_rn(h2[0] - __half2float(hi0));
                __half lo1 = __float2half_rn(h2[1] - __half2float(hi1));
                *phiO = __halves2half2(hi0, hi1);
                *ploO = __halves2half2(lo0, lo1);
                if (fin)
                    *(float2*)(out_f + m * HD + hcb) = make_float2(h2[0], h2[1]);
            } else {
                __half2 vh = *(const __half2*)(Ain + tb + off);
                __half2 vl = *(const __half2*)(Ain + tb + TIL + off);
                *phiO = vh;
                *ploO = vl;
                if (fin) {
                    float2 fh = __half22float2(vh);
                    float2 fl = __half22float2(vl);
                    *(float2*)(out_f + m * HD + hcb) =
                        make_float2(fh.x + fl.x, fh.y + fl.y);
                }
            }
        }
    }
}

// ------------------------------ host entry --------------------------------
// Inputs: char_seq_padded(i32), char_lengths(i32), emb, W_ih, W_hh, b_ih, b_hh
extern "C" void kernel_launch(void* const* d_in, const int* in_sizes, int n_in,
                              void* d_out, int out_size) {
    const int*   seq  = (const int*)  d_in[0];
    const int*   lens = (const int*)  d_in[1];
    const float* emb  = (const float*)d_in[2];
    const float* W_ih = (const float*)d_in[3];
    const float* W_hh = (const float*)d_in[4];
    const float* b_ih = (const float*)d_in[5];
    const float* b_hh = (const float*)d_in[6];
    float* out = (float*)d_out;

    cudaFuncSetAttribute(lstm_step,
                         cudaFuncAttributeMaxDynamicSharedMemorySize,
                         SMEM_TOTAL);

    prep_w<<<(G4 * HD) / 256, 256>>>(W_hh);
    prep_tbl<<<dim3(G4 / 128, NV), 128>>>(emb, W_ih, b_ih, b_hh);
    step0<<<dim3(BT, HD / 128), 128>>>(seq);

    for (int t = 1; t < SL; t++) {
        float* o = (t == SL - 1) ? out : nullptr;
        lstm_step<<<dim3(G4 / 128, BT / 128), 256, SMEM_TOTAL>>>(seq, lens, o, t);
    }
}

// round 10
// speedup vs baseline: 4.9157x; 1.5436x over previous
#include <cuda_runtime.h>
#include <cuda_fp16.h>
#include <cstdint>

// ===========================================================================
// CharLSTMEmbedding: B=32, T=128, L=16, VOCAB=256, E=256, H=512
// sm_103 plain target -> mma.sync HMMA + cp.async.bulk loads.
//
// R10:
//  * rows counting-sorted by length (descending). Active rows at step t form
//    prefix [0, M_t); CTAs beyond ceil(M_t/128) early-exit  -> ~2x less FLOP.
//    Each row writes d_out at its freeze step (lens == t+1).
//  * full/empty mbarrier producer-consumer pipeline replaces per-chunk
//    __syncthreads() -> warps run decoupled (up to 3-chunk skew).
//  * 2 CTAs/SM (regs=128), 3-stage 32KB bulk-copy pipeline, K-chunk 32.
//
//   tile: 128 rows x 32 halves, paired-row swizzle (2 rows / 128B line):
//     off(r,x) = (r>>1)*128 + (((r&1)*64 + x) ^ (((r>>1)&7)<<4))
//   n' permutation: n' = (hc>>3)*32 + g*8 + (hc&7)  (epilogue shuffle-free)
// ===========================================================================

#define BT   4096
#define SL   16
#define HD   512
#define ED   256
#define NV   256
#define G4   2048

#define TIL  8192              // one 128x32-half tile (hi or lo)
#define CK2  16384             // hi+lo pair
#define NCK  16                // K chunks of 32

__device__ __align__(1024) unsigned char g_W[16 * NCK * CK2];     // 4 MB
__device__ __align__(1024) unsigned char g_A[2][32 * NCK * CK2];  // 2 x 8 MB
__device__ __align__(256) float g_tbl[NV * G4];                   // 2 MB
__device__ __align__(256) float g_C[BT * HD];                     // 8 MB
__device__ int g_perm[BT];      // sorted-pos -> original row
__device__ int g_lens_s[BT];    // lens in sorted order (descending)
__device__ int g_Mt[SL];        // M_t = #(lens > t)

// ------------------------------ helpers -----------------------------------

__device__ __forceinline__ uint32_t smem_u32(const void* p) {
    uint32_t a;
    asm("{ .reg .u64 t; cvta.to.shared.u64 t, %1; cvt.u32.u64 %0, t; }"
        : "=r"(a) : "l"(p));
    return a;
}

// paired-row swizzle for 128row x 64B tiles
__device__ __forceinline__ uint32_t swz32(uint32_t r, uint32_t x) {
    return (r >> 1) * 128u + ((((r & 1u) << 6) + x) ^ ((r & 14u) << 3));
}

__device__ __forceinline__ void bulk_cp(uint32_t dst, const void* src,
                                        uint32_t bytes, uint32_t mbar) {
    asm volatile(
        "cp.async.bulk.shared::cluster.global.mbarrier::complete_tx::bytes "
        "[%0], [%1], %2, [%3];"
        :: "r"(dst), "l"(src), "r"(bytes), "r"(mbar) : "memory");
}

__device__ __forceinline__ void mbar_init(uint32_t mbar, uint32_t cnt) {
    asm volatile("mbarrier.init.shared.b64 [%0], %1;" :: "r"(mbar), "r"(cnt)
                 : "memory");
}
__device__ __forceinline__ void mbar_expect(uint32_t mbar, uint32_t bytes) {
    asm volatile("mbarrier.arrive.expect_tx.shared.b64 _, [%0], %1;"
                 :: "r"(mbar), "r"(bytes) : "memory");
}
__device__ __forceinline__ void mbar_arrive(uint32_t mbar) {
    asm volatile("mbarrier.arrive.shared.b64 _, [%0];" :: "r"(mbar) : "memory");
}
__device__ __forceinline__ void mbar_wait(uint32_t mbar, uint32_t parity) {
    asm volatile(
        "{\n\t.reg .pred P;\n\t"
        "WL_%=:\n\t"
        "mbarrier.try_wait.parity.acquire.cta.shared::cta.b64 P, [%0], %1, 0x989680;\n\t"
        "@P bra.uni WD_%=;\n\t"
        "bra.uni WL_%=;\n\t"
        "WD_%=:\n\t}"
        :: "r"(mbar), "r"(parity) : "memory");
}

__device__ __forceinline__ void ldsm4(uint32_t* r, uint32_t addr) {
    asm volatile("ldmatrix.sync.aligned.m8n8.x4.shared.b16 {%0,%1,%2,%3}, [%4];"
                 : "=r"(r[0]), "=r"(r[1]), "=r"(r[2]), "=r"(r[3]) : "r"(addr));
}
__device__ __forceinline__ void ldsm2(uint32_t* r, uint32_t addr) {
    asm volatile("ldmatrix.sync.aligned.m8n8.x2.shared.b16 {%0,%1}, [%2];"
                 : "=r"(r[0]), "=r"(r[1]) : "r"(addr));
}

__device__ __forceinline__ void mma16816(float* d, const uint32_t* a,
                                         const uint32_t* b) {
    asm volatile(
        "mma.sync.aligned.m16n8k16.row.col.f32.f16.f16.f32 "
        "{%0,%1,%2,%3}, {%4,%5,%6,%7}, {%8,%9}, {%0,%1,%2,%3};"
        : "+f"(d[0]), "+f"(d[1]), "+f"(d[2]), "+f"(d[3])
        : "r"(a[0]), "r"(a[1]), "r"(a[2]), "r"(a[3]), "r"(b[0]), "r"(b[1]));
}

__device__ __forceinline__ float sigf(float x) {
    return __fdividef(1.0f, 1.0f + __expf(-x));
}
__device__ __forceinline__ float tanhfast(float x) {
    return __fdividef(2.0f, 1.0f + __expf(-2.0f * x)) - 1.0f;
}

// ------------------------------ prep kernels ------------------------------

// counting sort by length, descending; deterministic within-bin order.
__global__ void prep_perm(const int* __restrict__ lens) {
    __shared__ int cnt[17], off[17];
    int tid = threadIdx.x;
    if (tid < 17) cnt[tid] = 0;
    __syncthreads();
    for (int i = tid; i < BT; i += 512) atomicAdd(&cnt[lens[i]], 1);
    __syncthreads();
    if (tid == 0) {
        int acc = 0;
        for (int l = 16; l >= 1; l--) { off[l] = acc; acc += cnt[l]; }
        g_Mt[0] = BT;
        for (int t = 1; t < SL; t++) g_Mt[t] = off[t];   // #(lens > t)
    }
    __syncthreads();
    int w = tid >> 5, lane = tid & 31;
    int l = w + 1;                                   // bins 1..16
    int p = off[l];
    for (int base = 0; base < BT; base += 32) {
        int i = base + lane;
        bool m = (lens[i] == l);
        unsigned msk = __ballot_sync(0xffffffffu, m);
        if (m) {
            int rank = __popc(msk & ((1u << lane) - 1));
            g_perm[p + rank] = i;
            g_lens_s[p + rank] = l;
        }
        p += __popc(msk);
    }
}

__global__ void prep_w(const float* __restrict__ W) {
    int idx = blockIdx.x * 256 + threadIdx.x;      // < G4*HD
    int np = idx >> 9, k = idx & 511;
    int hc = ((np >> 5) << 3) + (np & 7);
    int g  = (np >> 3) & 3;
    float v = W[(g * HD + hc) * HD + k];
    __half hi = __float2half_rn(v);
    __half lo = __float2half_rn(v - __half2float(hi));
    uint32_t base = (uint32_t)((np >> 7) * NCK + (k >> 5)) * CK2;
    uint32_t off  = swz32((uint32_t)(np & 127), (uint32_t)((k & 31) * 2));
    *(__half*)(g_W + base + off)       = hi;
    *(__half*)(g_W + base + TIL + off) = lo;
}

__global__ void prep_tbl(const float* __restrict__ emb,
                         const float* __restrict__ Wih,
                         const float* __restrict__ bi,
                         const float* __restrict__ bh) {
    __shared__ __align__(16) float e[ED];
    int v = blockIdx.y;
    for (int i = threadIdx.x; i < ED; i += blockDim.x)
        e[i] = emb[v * ED + i];
    __syncthreads();

    int np = blockIdx.x * 128 + threadIdx.x;
    int hc = ((np >> 5) << 3) + (np & 7);
    int g  = (np >> 3) & 3;
    int n  = g * HD + hc;
    const float4* w4 = (const float4*)(Wih + n * ED);
    const float4* e4 = (const float4*)e;
    float s = bi[n] + bh[n];
#pragma unroll 8
    for (int k = 0; k < ED / 4; k++) {
        float4 wv = w4[k];
        float4 ev = e4[k];
        s += ev.x * wv.x + ev.y * wv.y + ev.z * wv.z + ev.w * wv.w;
    }
    g_tbl[v * G4 + np] = s;
}

// step 0 in sorted row space; rows with lens==1 freeze here -> write out
__global__ void step0(const int* __restrict__ seq, float* __restrict__ out) {
    int ms = blockIdx.x;                       // sorted row
    int hc = blockIdx.y * 128 + threadIdx.x;
    int orig = g_perm[ms];
    int id = seq[orig * SL];
    int base = ((hc >> 3) << 5) + (hc & 7);    // gate stride 8 in tbl
    const float* tr = g_tbl + id * G4;
    float cn = sigf(tr[base]) * tanhfast(tr[base + 16]);
    float hn = sigf(tr[base + 24]) * tanhfast(cn);
    __half hi = __float2half_rn(hn);
    __half lo = __float2half_rn(hn - __half2float(hi));
    uint32_t tb  = (uint32_t)((ms >> 7) * NCK + (hc >> 5)) * CK2;
    uint32_t off = swz32((uint32_t)(ms & 127), (uint32_t)((hc & 31) * 2));
    *(__half*)(g_A[0] + tb + off)       = hi;
    *(__half*)(g_A[0] + tb + TIL + off) = lo;
    g_C[ms * HD + hc] = cn;
    if (g_lens_s[ms] == 1) out[orig * HD + hc] = hn;
}

// --------------------------- recurrent step -------------------------------
// CTA 128(m) x 128(n'), 256 threads, 8 warps (2m x 4n), warp 64x32.
// 16 K-chunks of 32; 3-stage pipeline with full (tx) + empty (count 8) mbars.

#define SMEM_TOTAL (1024 + 3 * 32768)

__global__ void __launch_bounds__(256, 2)
lstm_step(const int* __restrict__ seq, float* __restrict__ out_f, int t) {
    // active-prefix early exit
    const int m0 = (int)blockIdx.y * 128;
    const int Mpad = (g_Mt[t] + 127) & ~127;
    if (m0 >= Mpad) return;

    extern __shared__ char smem[];
    const uint32_t sb = smem_u32(smem);
    const int tid = threadIdx.x, lid = tid & 31;
    const int wm = (tid >> 5) >> 2;            // 0..1
    const int wn = (tid >> 5) & 3;             // 0..3

    const unsigned char* __restrict__ Asrc =
        g_A[(t + 1) & 1] + (size_t)blockIdx.y * NCK * CK2;
    const unsigned char* __restrict__ Wsrc =
        g_W + (size_t)blockIdx.x * NCK * CK2;

    // mbars: full[b] @ sb+b*8 (count1, tx), empty[b] @ sb+24+b*8 (count 8)
    if (tid == 0) {
#pragma unroll
        for (int b = 0; b < 3; b++) {
            mbar_init(sb + b * 8, 1);
            mbar_init(sb + 24 + b * 8, 8);
        }
    }
    __syncthreads();

    auto issue = [&](int ck) {
        uint32_t buf = (uint32_t)(ck % 3);
        uint32_t dst = sb + 1024 + buf * 32768;
        uint32_t mb  = sb + buf * 8;
        mbar_expect(mb, 32768);
        bulk_cp(dst,       Asrc + ck * CK2, CK2, mb);   // Ahi|Alo
        bulk_cp(dst + CK2, Wsrc + ck * CK2, CK2, mb);   // Bhi|Blo
    };
    if (tid == 0) { issue(0); issue(1); issue(2); }

    float acc[4][4][4];
#pragma unroll
    for (int a = 0; a < 4; a++)
#pragma unroll
        for (int b = 0; b < 4; b++)
#pragma unroll
            for (int c = 0; c < 4; c++) acc[a][b][c] = 0.0f;

    const uint32_t arow = (uint32_t)(wm * 64 + (lid & 15));
    const uint32_t acs  = (uint32_t)((lid >> 4) * 16);        // A k-seg
    const uint32_t brow = (uint32_t)(wn * 32 + (lid & 7));
    const uint32_t bcs  = (uint32_t)(((lid >> 3) & 1) * 16);  // B k-seg

    for (int ck = 0; ck < NCK; ck++) {
        const uint32_t buf = (uint32_t)(ck % 3);
        const uint32_t par = (uint32_t)((ck / 3) & 1);
        mbar_wait(sb + buf * 8, par);                 // full

        const uint32_t cb = sb + 1024 + buf * 32768;
        const uint32_t sAhi = cb, sAlo = cb + TIL;
        const uint32_t sBhi = cb + 2 * TIL, sBlo = cb + 3 * TIL;

#pragma unroll
        for (int k16 = 0; k16 < 2; k16++) {
            const uint32_t ax = (uint32_t)(k16 * 32) + acs;
            const uint32_t bx = (uint32_t)(k16 * 32) + bcs;
            uint32_t bhf[4][2], blf[4][2];
#pragma unroll
            for (int g = 0; g < 4; g++) {
                uint32_t ro = swz32(brow + (uint32_t)(g * 8), bx);
                ldsm2(bhf[g], sBhi + ro);
                ldsm2(blf[g], sBlo + ro);
            }
#pragma unroll
            for (int mt = 0; mt < 4; mt++) {
                uint32_t ro = swz32(arow + (uint32_t)(mt * 16), ax);
                uint32_t ah[4], al[4];
                ldsm4(ah, sAhi + ro);
                ldsm4(al, sAlo + ro);
                // term-major: consecutive MMAs hit different accumulators
#pragma unroll
                for (int g = 0; g < 4; g++) mma16816(acc[mt][g], ah, bhf[g]);
#pragma unroll
                for (int g = 0; g < 4; g++) mma16816(acc[mt][g], ah, blf[g]);
#pragma unroll
                for (int g = 0; g < 4; g++) mma16816(acc[mt][g], al, bhf[g]);
            }
        }
        if (lid == 0) mbar_arrive(sb + 24 + buf * 8);  // this warp done
        if (tid == 0 && ck + 3 < NCK) {
            mbar_wait(sb + 24 + buf * 8, par);         // all 8 warps done
            issue(ck + 3);
        }
    }

    // ---------------- fused LSTM epilogue ----------------
    const int q = lid & 3, r = lid >> 2;
    const int n0 = blockIdx.x * 128;
    const int cn0 = n0 + wn * 32;
    const int hcb = (cn0 >> 2) + 2 * q;            // even, pair (hcb, hcb+1)
    unsigned char* __restrict__ Aout = g_A[t & 1];
    const unsigned char* __restrict__ Ain = g_A[(t + 1) & 1];

    const uint32_t ckh  = (uint32_t)(hcb >> 5);
    const uint32_t xoff = (uint32_t)((hcb & 31) * 2);

#pragma unroll
    for (int mt = 0; mt < 4; mt++) {
#pragma unroll
        for (int v = 0; v < 2; v++) {
            const int ms = m0 + wm * 64 + mt * 16 + r + v * 8;   // sorted row
            const int L  = g_lens_s[ms];
            const bool act = L > t;
            const uint32_t tb  = ((uint32_t)(ms >> 7) * NCK + ckh) * CK2;
            const uint32_t off = swz32((uint32_t)(ms & 127), xoff);
            __half2* phiO = (__half2*)(Aout + tb + off);
            __half2* ploO = (__half2*)(Aout + tb + TIL + off);
            if (act) {
                const int orig = g_perm[ms];
                const int id = seq[orig * SL + t];
                const float* tr = g_tbl + id * G4 + cn0 + 2 * q;
                float2 cp = *(const float2*)(g_C + ms * HD + hcb);
                float co[2] = {cp.x, cp.y};
                float h2[2], c2[2];
#pragma unroll
                for (int j = 0; j < 2; j++) {
                    float pi = acc[mt][0][2 * v + j] + tr[0 + j];
                    float pf = acc[mt][1][2 * v + j] + tr[8 + j];
                    float pg = acc[mt][2][2 * v + j] + tr[16 + j];
                    float po = acc[mt][3][2 * v + j] + tr[24 + j];
                    float ig = sigf(pi), fg = sigf(pf);
                    float gg = tanhfast(pg), og = sigf(po);
                    float cc = fg * co[j] + ig * gg;
                    c2[j] = cc;
                    h2[j] = og * tanhfast(cc);
                }
                *(float2*)(g_C + ms * HD + hcb) = make_float2(c2[0], c2[1]);
                __half hi0 = __float2half_rn(h2[0]);
                __half hi1 = __float2half_rn(h2[1]);
                __half lo0 = __float2half_rn(h2[0] - __half2float(hi0));
                __half lo1 = __float2half_rn(h2[1] - __half2float(hi1));
                *phiO = __halves2half2(hi0, hi1);
                *ploO = __halves2half2(lo0, lo1);
                if (L == t + 1)                        // freezes after this
                    *(float2*)(out_f + orig * HD + hcb) =
                        make_float2(h2[0], h2[1]);
            } else {
                // frozen boundary-tile row: forward state for ping-pong
                *phiO = *(const __half2*)(Ain + tb + off);
                *ploO = *(const __half2*)(Ain + tb + TIL + off);
            }
        }
    }
}

// ------------------------------ host entry --------------------------------
// Inputs: char_seq_padded(i32), char_lengths(i32), emb, W_ih, W_hh, b_ih, b_hh
extern "C" void kernel_launch(void* const* d_in, const int* in_sizes, int n_in,
                              void* d_out, int out_size) {
    const int*   seq  = (const int*)  d_in[0];
    const int*   lens = (const int*)  d_in[1];
    const float* emb  = (const float*)d_in[2];
    const float* W_ih = (const float*)d_in[3];
    const float* W_hh = (const float*)d_in[4];
    const float* b_ih = (const float*)d_in[5];
    const float* b_hh = (const float*)d_in[6];
    float* out = (float*)d_out;

    cudaFuncSetAttribute(lstm_step,
                         cudaFuncAttributeMaxDynamicSharedMemorySize,
                         SMEM_TOTAL);

    prep_perm<<<1, 512>>>(lens);
    prep_w<<<(G4 * HD) / 256, 256>>>(W_hh);
    prep_tbl<<<dim3(G4 / 128, NV), 128>>>(emb, W_ih, b_ih, b_hh);
    step0<<<dim3(BT, HD / 128), 128>>>(seq, out);

    for (int t = 1; t < SL; t++)
        lstm_step<<<dim3(G4 / 128, BT / 128), 256, SMEM_TOTAL>>>(seq, out, t);
}